// round 4
// baseline (speedup 1.0000x reference)
#include <cuda_runtime.h>
#include <cstddef>

#define N_NODES 12288
#define IN_F    256
#define OUT_F   64
#define JSPLIT  3
#define BI      128
#define JT      32
#define JRANGE  (N_NODES / JSPLIT)   // 4096

// ---------------- scratch (no allocations allowed) ----------------
__device__ float g_h[N_NODES * OUT_F];                 // 3 MB
__device__ float g_part[JSPLIT][N_NODES * OUT_F];      // 9.4 MB
__device__ int   g_deg[JSPLIT][N_NODES];

// ---------------- packed f32x2 helpers ----------------
__device__ __forceinline__ unsigned long long pack2(float x) {
    unsigned long long r;
    asm("mov.b64 %0, {%1, %1};" : "=l"(r) : "f"(x));
    return r;
}
__device__ __forceinline__ void ffma2(unsigned long long& acc,
                                      unsigned long long a,
                                      unsigned long long b) {
    asm("fma.rn.f32x2 %0, %1, %2, %0;" : "+l"(acc) : "l"(a), "l"(b));
}
__device__ __forceinline__ float2 unpack2(unsigned long long v) {
    float2 r;
    asm("mov.b64 {%0, %1}, %2;" : "=f"(r.x), "=f"(r.y) : "l"(v));
    return r;
}

// ======================= Kernel 1: h = x @ W =======================
// grid 384, block 256. Block covers 32 rows. thread: ti=row, tf=f-group of 8.
__global__ void __launch_bounds__(256)
k_gemm_h(const float* __restrict__ x, const float* __restrict__ W) {
    __shared__ float x_s[32][IN_F + 1];   // padded: bank = (row+k)%32
    const int tid = threadIdx.x;
    const int ti  = tid & 31;
    const int tf  = tid >> 5;             // 0..7
    const int rBase = blockIdx.x * 32;

    // stage x: 32*256 floats = 2048 float4, 8 per thread
    #pragma unroll
    for (int k = 0; k < 8; k++) {
        int idx = tid + k * 256;          // float4 index
        int row = idx >> 6;               // 64 float4 per row
        int c4  = (idx & 63) << 2;
        float4 v = *reinterpret_cast<const float4*>(
            x + (size_t)(rBase + row) * IN_F + c4);
        x_s[row][c4 + 0] = v.x; x_s[row][c4 + 1] = v.y;
        x_s[row][c4 + 2] = v.z; x_s[row][c4 + 3] = v.w;
    }
    __syncthreads();

    float acc[8] = {0.f,0.f,0.f,0.f,0.f,0.f,0.f,0.f};
    #pragma unroll 4
    for (int k = 0; k < IN_F; k++) {
        float xv = x_s[ti][k];
        const float4* wp = reinterpret_cast<const float4*>(W + k * OUT_F + tf * 8);
        float4 w0 = wp[0];
        float4 w1 = wp[1];
        acc[0] += xv * w0.x; acc[1] += xv * w0.y;
        acc[2] += xv * w0.z; acc[3] += xv * w0.w;
        acc[4] += xv * w1.x; acc[5] += xv * w1.y;
        acc[6] += xv * w1.z; acc[7] += xv * w1.w;
    }

    float* hp = &g_h[(size_t)(rBase + ti) * OUT_F + tf * 8];
    *reinterpret_cast<float4*>(hp + 0) = make_float4(acc[0], acc[1], acc[2], acc[3]);
    *reinterpret_cast<float4*>(hp + 4) = make_float4(acc[4], acc[5], acc[6], acc[7]);
}

// ========== Kernel 2: partial[js][i,f] = sum_{j in split} mask(adj) * h[j,f] ==========
// grid (96, 3), block 256. BLOCK_I=128 rows, JT=32 per tile.
// thread: ti = tid&31 (i-lane), tf = tid>>5 (f-group). Each thread: 4 i-rows x 8 f.
__global__ void __launch_bounds__(256)
k_aggregate(const int* __restrict__ adj) {
    __shared__ float adj_s[BI][JT + 1];                 // padded vs bank conflicts
    __shared__ __align__(16) float h_s[JT][OUT_F];
    __shared__ int degs_s[BI];

    const int tid   = threadIdx.x;
    const int ti    = tid & 31;
    const int tf    = tid >> 5;                         // 0..7
    const int iBase = blockIdx.x * BI;
    const int js    = blockIdx.y;
    const int jBeg  = js * JRANGE;

    if (tid < BI) degs_s[tid] = 0;

    unsigned long long acc[4][4];
    #pragma unroll
    for (int r = 0; r < 4; r++)
        #pragma unroll
        for (int c = 0; c < 4; c++) acc[r][c] = 0ULL;

    __syncthreads();

    for (int j0 = jBeg; j0 < jBeg + JRANGE; j0 += JT) {
        // ---- stage adj tile (128 x 32 ints = 1024 int4, 4 per thread) + degree ----
        #pragma unroll
        for (int k = 0; k < 4; k++) {
            int idx = tid + k * 256;                    // int4 index
            int row = idx >> 3;                         // 8 int4 per row
            int c4  = (idx & 7) << 2;
            int4 v = *reinterpret_cast<const int4*>(
                adj + (size_t)(iBase + row) * N_NODES + j0 + c4);
            int m0 = (v.x > 0), m1 = (v.y > 0), m2 = (v.z > 0), m3 = (v.w > 0);
            adj_s[row][c4 + 0] = (float)m0;
            adj_s[row][c4 + 1] = (float)m1;
            adj_s[row][c4 + 2] = (float)m2;
            adj_s[row][c4 + 3] = (float)m3;
            atomicAdd(&degs_s[row], m0 + m1 + m2 + m3);
        }
        // ---- stage h tile (32 x 64 floats = 512 float4, 2 per thread) ----
        #pragma unroll
        for (int k = 0; k < 2; k++) {
            int idx = tid + k * 256;                    // float4 index
            int row = idx >> 4;                         // 16 float4 per row
            int c4  = (idx & 15) << 2;
            *reinterpret_cast<float4*>(&h_s[row][c4]) =
                *reinterpret_cast<const float4*>(g_h + (size_t)(j0 + row) * OUT_F + c4);
        }
        __syncthreads();

        #pragma unroll 8
        for (int jj = 0; jj < JT; jj++) {
            const ulonglong2* hp =
                reinterpret_cast<const ulonglong2*>(&h_s[jj][tf * 8]);
            ulonglong2 hv01 = hp[0];    // features f+0..3 (packed pairs)
            ulonglong2 hv23 = hp[1];    // features f+4..7
            #pragma unroll
            for (int r = 0; r < 4; r++) {
                float av = adj_s[ti + 32 * r][jj];
                unsigned long long ap = pack2(av);
                ffma2(acc[r][0], ap, hv01.x);
                ffma2(acc[r][1], ap, hv01.y);
                ffma2(acc[r][2], ap, hv23.x);
                ffma2(acc[r][3], ap, hv23.y);
            }
        }
        __syncthreads();
    }

    // ---- epilogue: write partials + degrees ----
    #pragma unroll
    for (int r = 0; r < 4; r++) {
        int i = iBase + ti + 32 * r;
        float2 p0 = unpack2(acc[r][0]);
        float2 p1 = unpack2(acc[r][1]);
        float2 p2 = unpack2(acc[r][2]);
        float2 p3 = unpack2(acc[r][3]);
        float* op = &g_part[js][(size_t)i * OUT_F + tf * 8];
        *reinterpret_cast<float4*>(op + 0) = make_float4(p0.x, p0.y, p1.x, p1.y);
        *reinterpret_cast<float4*>(op + 4) = make_float4(p2.x, p2.y, p3.x, p3.y);
    }
    if (tid < BI) g_deg[js][iBase + tid] = degs_s[tid];
}

// ================ Kernel 3: out = elu(sum(partials)/deg) ================
__global__ void __launch_bounds__(256)
k_finalize(float* __restrict__ out) {
    int g = blockIdx.x * 256 + threadIdx.x;            // < 12288*64
    int i = g >> 6;
    float s = g_part[0][g] + g_part[1][g] + g_part[2][g];
    float d = (float)(g_deg[0][i] + g_deg[1][i] + g_deg[2][i]);
    float v = s / d;
    out[g] = (v > 0.f) ? v : expm1f(v);
}

// =========================== launch ===========================
extern "C" void kernel_launch(void* const* d_in, const int* in_sizes, int n_in,
                              void* d_out, int out_size) {
    // Identify inputs by element count (robust to metadata ordering):
    // adj: 12288*12288, x: 12288*256, W: 256*64, a: 128 (unused)
    const int* adj = nullptr;
    const float* x = nullptr;
    const float* W = nullptr;
    for (int k = 0; k < n_in; k++) {
        long long sz = in_sizes[k];
        if (sz == (long long)N_NODES * N_NODES) adj = (const int*)d_in[k];
        else if (sz == (long long)N_NODES * IN_F) x = (const float*)d_in[k];
        else if (sz == (long long)IN_F * OUT_F)   W = (const float*)d_in[k];
    }
    float* out = (float*)d_out;

    k_gemm_h<<<N_NODES / 32, 256>>>(x, W);
    k_aggregate<<<dim3(N_NODES / BI, JSPLIT), 256>>>(adj);
    k_finalize<<<(N_NODES * OUT_F) / 256, 256>>>(out);
}

// round 6
// speedup vs baseline: 2.9978x; 2.9978x over previous
#include <cuda_runtime.h>
#include <cuda_bf16.h>
#include <cstdint>
#include <cstddef>

#define N_NODES 12288
#define IN_F    256
#define OUT_F   64
#define JSPLIT  3
#define JRANGE  (N_NODES / JSPLIT)   // 4096
#define BI      64                   // i-rows per CTA
#define TJ      64                   // k per tile
#define NTILES  (JRANGE / TJ)        // 64

// h split to bf16 hi/lo, transposed: g_bt[n][j], n in [0,128)
__device__ __nv_bfloat16 g_bt[128 * N_NODES];          // 3.1 MB
__device__ float g_part[JSPLIT][N_NODES * OUT_F];      // 9.4 MB
__device__ int   g_deg[JSPLIT][N_NODES];

// ---------------- helpers ----------------
__device__ __forceinline__ uint32_t smem_u32(const void* p) {
    uint32_t a;
    asm("{ .reg .u64 t; cvta.to.shared.u64 t, %1; cvt.u32.u64 %0, t; }"
        : "=r"(a) : "l"(p));
    return a;
}
__device__ __forceinline__ void sts64(uint32_t addr, uint32_t a, uint32_t b) {
    asm volatile("st.shared.v2.b32 [%0], {%1,%2};" :: "r"(addr), "r"(a), "r"(b) : "memory");
}
__device__ __forceinline__ void cp_async16(uint32_t dst, const void* src) {
    asm volatile("cp.async.cg.shared.global [%0], [%1], 16;" :: "r"(dst), "l"(src) : "memory");
}
__device__ __forceinline__ void ldsm4(uint32_t* r, uint32_t addr) {
    asm volatile("ldmatrix.sync.aligned.m8n8.x4.shared.b16 {%0,%1,%2,%3}, [%4];"
        : "=r"(r[0]), "=r"(r[1]), "=r"(r[2]), "=r"(r[3]) : "r"(addr));
}
__device__ __forceinline__ void mma16816(float* c, const uint32_t* a,
                                         uint32_t b0, uint32_t b1) {
    asm volatile(
        "mma.sync.aligned.m16n8k16.row.col.f32.bf16.bf16.f32 "
        "{%0,%1,%2,%3},{%4,%5,%6,%7},{%8,%9},{%0,%1,%2,%3};"
        : "+f"(c[0]), "+f"(c[1]), "+f"(c[2]), "+f"(c[3])
        : "r"(a[0]), "r"(a[1]), "r"(a[2]), "r"(a[3]), "r"(b0), "r"(b1));
}
__device__ __forceinline__ uint32_t sw128(uint32_t off) {
    return off ^ ((off >> 3) & 0x70u);
}

// ======================= Kernel 1: h = x @ W, bf16-split + transpose =======================
__global__ void __launch_bounds__(256)
k_gemm_h(const float* __restrict__ x, const float* __restrict__ W) {
    __shared__ float x_s[32][IN_F + 1];
    __shared__ float w_s[32][OUT_F];
    const int tid = threadIdx.x;
    const int ti  = tid & 31;
    const int tf  = tid >> 5;
    const int rBase = blockIdx.x * 32;

    #pragma unroll
    for (int k = 0; k < 8; k++) {
        int idx = tid + k * 256;
        int row = idx >> 6;
        int c4  = (idx & 63) << 2;
        float4 v = *reinterpret_cast<const float4*>(
            x + (size_t)(rBase + row) * IN_F + c4);
        x_s[row][c4 + 0] = v.x; x_s[row][c4 + 1] = v.y;
        x_s[row][c4 + 2] = v.z; x_s[row][c4 + 3] = v.w;
    }

    float acc[8] = {0.f,0.f,0.f,0.f,0.f,0.f,0.f,0.f};
    for (int kc = 0; kc < 8; kc++) {
        __syncthreads();
        #pragma unroll
        for (int m = 0; m < 2; m++) {
            int idx = tid + m * 256;
            int row = idx >> 4;
            int c4  = (idx & 15) << 2;
            *reinterpret_cast<float4*>(&w_s[row][c4]) =
                *reinterpret_cast<const float4*>(W + (size_t)(kc * 32 + row) * OUT_F + c4);
        }
        __syncthreads();
        #pragma unroll 8
        for (int kk = 0; kk < 32; kk++) {
            float xv = x_s[ti][kc * 32 + kk];
            float4 w0 = *reinterpret_cast<const float4*>(&w_s[kk][tf * 8]);
            float4 w1 = *reinterpret_cast<const float4*>(&w_s[kk][tf * 8 + 4]);
            acc[0] += xv * w0.x; acc[1] += xv * w0.y;
            acc[2] += xv * w0.z; acc[3] += xv * w0.w;
            acc[4] += xv * w1.x; acc[5] += xv * w1.y;
            acc[6] += xv * w1.z; acc[7] += xv * w1.w;
        }
    }

    int j = rBase + ti;
    #pragma unroll
    for (int u = 0; u < 8; u++) {
        int f = tf * 8 + u;
        __nv_bfloat16 bh = __float2bfloat16(acc[u]);
        float lo = acc[u] - __bfloat162float(bh);
        __nv_bfloat16 bl = __float2bfloat16(lo);
        g_bt[(size_t)f * N_NODES + j]        = bh;
        g_bt[(size_t)(64 + f) * N_NODES + j] = bl;
    }
}

// ======================= Kernel 2: HMMA masked aggregation =======================
// partial[js][i, 0:64] = sum_{j in split} mask[i,j] * h[j,:]   (hi+lo combined)
// smem: A bf16 [2][64][64] @0 (16KB), B bf16 [3][128][64] @16384 (48KB)
__global__ void __launch_bounds__(256, 2)
k_aggregate(const int* __restrict__ adj) {
    extern __shared__ __align__(1024) unsigned char smem[];
    const int tid   = threadIdx.x;
    const int lane  = tid & 31;
    const int w     = tid >> 5;
    const int wm    = w & 1;          // M half (32 rows)
    const int wn    = w >> 1;         // N quarter (32 feats)
    const int iBase = blockIdx.x * BI;
    const int js    = blockIdx.y;
    const int jBeg  = js * JRANGE;

    uint32_t sbase = (smem_u32(smem) + 1023u) & ~1023u;
    const uint32_t offA = sbase;
    const uint32_t offB = sbase + 16384;

    // ---- staging geometry ----
    const int4* aP[4];
    uint32_t a_sw[4];
    #pragma unroll
    for (int k = 0; k < 4; k++) {
        int idx  = k * 256 + tid;
        int arow = idx >> 4, acol = idx & 15;       // 16 int4 per 64-int row
        aP[k]   = reinterpret_cast<const int4*>(
                      adj + (size_t)(iBase + arow) * N_NODES + jBeg) + acol;
        a_sw[k] = sw128((uint32_t)(arow * 128 + acol * 8));
    }
    const __nv_bfloat16* bSrc[4];
    uint32_t b_sw[4];
    #pragma unroll
    for (int k = 0; k < 4; k++) {
        int idx  = k * 256 + tid;
        int brow = idx >> 3, bcol = idx & 7;        // 8x16B per 128B row
        bSrc[k] = g_bt + (size_t)brow * N_NODES + jBeg + bcol * 8;
        b_sw[k] = sw128((uint32_t)(brow * 128 + bcol * 16));
    }

    // ---- ldmatrix lane geometry (precomputed swizzle row terms) ----
    const int a_r  = lane & 15;
    const uint32_t a_ch = (lane >> 4) << 4;         // 0 or 16 bytes
    const int rA0 = wm * 32 + a_r, rA1 = rA0 + 16;
    const uint32_t aRow0 = (uint32_t)(rA0 * 128 + ((rA0 & 7) << 4));
    const uint32_t aRow1 = (uint32_t)(rA1 * 128 + ((rA1 & 7) << 4));
    const int b_n  = (lane & 7) + ((lane >> 4) << 3);
    const uint32_t b_cb = (lane & 8) ? 16u : 0u;
    const int rB0 = wn * 32 + b_n, rB1 = rB0 + 16;
    const uint32_t bRow0 = (uint32_t)(rB0 * 128 + ((rB0 & 7) << 4));
    const uint32_t bRow1 = (uint32_t)(rB1 * 128 + ((rB1 & 7) << 4));

    // ---- prologue: B(0) via cp.async, A(0) via LDG ----
    #pragma unroll
    for (int k = 0; k < 4; k++) { cp_async16(offB + b_sw[k], bSrc[k]); bSrc[k] += 64; }
    asm volatile("cp.async.commit_group;" ::: "memory");
    int4 rA[4];
    #pragma unroll
    for (int k = 0; k < 4; k++) { rA[k] = __ldg(aP[k]); aP[k] += 16; }

    float acc[2][4][4];
    #pragma unroll
    for (int mi = 0; mi < 2; mi++)
        #pragma unroll
        for (int nj = 0; nj < 4; nj++)
            #pragma unroll
            for (int q = 0; q < 4; q++) acc[mi][nj][q] = 0.f;
    int dacc[4] = {0, 0, 0, 0};

    for (int t = 0; t < NTILES; t++) {
        const uint32_t aBase = offA + (uint32_t)(t & 1) * 8192;
        const uint32_t bBase = offB + (uint32_t)(t % 3) * 16384;

        // 1. convert + STS A(t); degree via dp4a
        #pragma unroll
        for (int k = 0; k < 4; k++) {
            uint32_t t0 = __byte_perm((uint32_t)rA[k].x, (uint32_t)rA[k].y, 0x7430);
            uint32_t t1 = __byte_perm((uint32_t)rA[k].z, (uint32_t)rA[k].w, 0x7430);
            dacc[k] = __dp4a((int)t0, 0x01010101, dacc[k]);
            dacc[k] = __dp4a((int)t1, 0x01010101, dacc[k]);
            sts64(aBase + a_sw[k], t0 * 0x3F80u, t1 * 0x3F80u);
        }
        // 2. prefetch tile t+1
        if (t + 1 < NTILES) {
            uint32_t bDst = offB + (uint32_t)((t + 1) % 3) * 16384;
            #pragma unroll
            for (int k = 0; k < 4; k++) { cp_async16(bDst + b_sw[k], bSrc[k]); bSrc[k] += 64; }
            asm volatile("cp.async.commit_group;" ::: "memory");
            #pragma unroll
            for (int k = 0; k < 4; k++) { rA[k] = __ldg(aP[k]); aP[k] += 16; }
            asm volatile("cp.async.wait_group 1;" ::: "memory");
        } else {
            asm volatile("cp.async.wait_group 0;" ::: "memory");
        }
        __syncthreads();

        // 3. MMA on tile t
        #pragma unroll
        for (int kk = 0; kk < 4; kk++) {
            const uint32_t cb = (uint32_t)(kk * 32);
            uint32_t A0[4], A1[4], B0[4], B1[4];
            ldsm4(A0, (aBase + aRow0) ^ (cb + a_ch));
            ldsm4(A1, (aBase + aRow1) ^ (cb + a_ch));
            ldsm4(B0, (bBase + bRow0) ^ (cb + b_cb));
            ldsm4(B1, (bBase + bRow1) ^ (cb + b_cb));
            mma16816(acc[0][0], A0, B0[0], B0[1]);
            mma16816(acc[0][1], A0, B0[2], B0[3]);
            mma16816(acc[0][2], A0, B1[0], B1[1]);
            mma16816(acc[0][3], A0, B1[2], B1[3]);
            mma16816(acc[1][0], A1, B0[0], B0[1]);
            mma16816(acc[1][1], A1, B0[2], B0[3]);
            mma16816(acc[1][2], A1, B1[0], B1[1]);
            mma16816(acc[1][3], A1, B1[2], B1[3]);
        }
    }

    // ---- epilogue: stage C (64 x 128) in smem (aliases B buffers), combine hi+lo ----
    __syncthreads();
    float* sC = reinterpret_cast<float*>(smem + (offB - smem_u32(smem)));
    const int g  = lane >> 2;
    const int cp = (lane & 3) * 2;
    #pragma unroll
    for (int mi = 0; mi < 2; mi++) {
        int r = wm * 32 + mi * 16 + g;
        #pragma unroll
        for (int nj = 0; nj < 4; nj++) {
            int col = wn * 32 + nj * 8 + cp;
            sC[r * 136 + col]           = acc[mi][nj][0];
            sC[r * 136 + col + 1]       = acc[mi][nj][1];
            sC[(r + 8) * 136 + col]     = acc[mi][nj][2];
            sC[(r + 8) * 136 + col + 1] = acc[mi][nj][3];
        }
    }
    __syncthreads();

    // combined partial: 64 rows x 64 feats; thread: row tid/4, feats (tid%4)*16..+15
    {
        int r  = tid >> 2;
        int f0 = (tid & 3) * 16;
        float* dst = &g_part[js][(size_t)(iBase + r) * OUT_F + f0];
        #pragma unroll
        for (int u = 0; u < 16; u += 4) {
            float4 v;
            v.x = sC[r * 136 + f0 + u + 0] + sC[r * 136 + 64 + f0 + u + 0];
            v.y = sC[r * 136 + f0 + u + 1] + sC[r * 136 + 64 + f0 + u + 1];
            v.z = sC[r * 136 + f0 + u + 2] + sC[r * 136 + 64 + f0 + u + 2];
            v.w = sC[r * 136 + f0 + u + 3] + sC[r * 136 + 64 + f0 + u + 3];
            *reinterpret_cast<float4*>(dst + u) = v;
        }
    }

    // degree: dacc[k] covers row k*16 + (tid>>4), partials across lanes (tid&15)
    #pragma unroll
    for (int k = 0; k < 4; k++) {
        int v = dacc[k];
        v += __shfl_down_sync(0xffffffffu, v, 8, 16);
        v += __shfl_down_sync(0xffffffffu, v, 4, 16);
        v += __shfl_down_sync(0xffffffffu, v, 2, 16);
        v += __shfl_down_sync(0xffffffffu, v, 1, 16);
        if ((tid & 15) == 0)
            g_deg[js][iBase + k * 16 + (tid >> 4)] = v;
    }
}

// ================ Kernel 3: out = elu(sum(partials)/deg) ================
__global__ void __launch_bounds__(256)
k_finalize(float* __restrict__ out) {
    int g = blockIdx.x * 256 + threadIdx.x;
    int i = g >> 6;
    float s = g_part[0][g] + g_part[1][g] + g_part[2][g];
    float d = (float)(g_deg[0][i] + g_deg[1][i] + g_deg[2][i]);
    float v = s / d;
    out[g] = (v > 0.f) ? v : expm1f(v);
}

// =========================== launch ===========================
#define SMEM_AGG (16384 + 49152 + 1024)

extern "C" void kernel_launch(void* const* d_in, const int* in_sizes, int n_in,
                              void* d_out, int out_size) {
    const int* adj = nullptr;
    const float* x = nullptr;
    const float* W = nullptr;
    for (int k = 0; k < n_in; k++) {
        long long sz = in_sizes[k];
        if (sz == (long long)N_NODES * N_NODES)      adj = (const int*)d_in[k];
        else if (sz == (long long)N_NODES * IN_F)    x = (const float*)d_in[k];
        else if (sz == (long long)IN_F * OUT_F)      W = (const float*)d_in[k];
    }
    float* out = (float*)d_out;

    cudaFuncSetAttribute(k_aggregate, cudaFuncAttributeMaxDynamicSharedMemorySize, SMEM_AGG);

    k_gemm_h<<<N_NODES / 32, 256>>>(x, W);
    k_aggregate<<<dim3(N_NODES / BI, JSPLIT), 256, SMEM_AGG>>>(adj);
    k_finalize<<<(N_NODES * OUT_F) / 256, 256>>>(out);
}

// round 7
// speedup vs baseline: 3.3204x; 1.1076x over previous
#include <cuda_runtime.h>
#include <cuda_bf16.h>
#include <cstdint>
#include <cstddef>

#define N_NODES 12288
#define IN_F    256
#define OUT_F   64
#define JSPLIT  3
#define JRANGE  (N_NODES / JSPLIT)   // 4096
#define BI      128                  // i-rows per CTA
#define TJ      64                   // k per tile
#define NTILES  (JRANGE / TJ)        // 64

// h split to bf16 hi/lo, transposed: g_bt[n][j], n in [0,128)
__device__ __nv_bfloat16 g_bt[128 * N_NODES];          // 3.1 MB
__device__ float g_part[JSPLIT][N_NODES * OUT_F];      // 9.4 MB
__device__ int   g_deg[JSPLIT][N_NODES];

// ---------------- helpers ----------------
__device__ __forceinline__ uint32_t smem_u32(const void* p) {
    uint32_t a;
    asm("{ .reg .u64 t; cvta.to.shared.u64 t, %1; cvt.u32.u64 %0, t; }"
        : "=r"(a) : "l"(p));
    return a;
}
__device__ __forceinline__ void sts64(uint32_t addr, uint32_t a, uint32_t b) {
    asm volatile("st.shared.v2.b32 [%0], {%1,%2};" :: "r"(addr), "r"(a), "r"(b) : "memory");
}
__device__ __forceinline__ void cp_async16(uint32_t dst, const void* src) {
    asm volatile("cp.async.cg.shared.global [%0], [%1], 16;" :: "r"(dst), "l"(src) : "memory");
}
__device__ __forceinline__ void ldsm4(uint32_t* r, uint32_t addr) {
    asm volatile("ldmatrix.sync.aligned.m8n8.x4.shared.b16 {%0,%1,%2,%3}, [%4];"
        : "=r"(r[0]), "=r"(r[1]), "=r"(r[2]), "=r"(r[3]) : "r"(addr));
}
__device__ __forceinline__ void mma16816(float* c, const uint32_t* a,
                                         uint32_t b0, uint32_t b1) {
    asm volatile(
        "mma.sync.aligned.m16n8k16.row.col.f32.bf16.bf16.f32 "
        "{%0,%1,%2,%3},{%4,%5,%6,%7},{%8,%9},{%0,%1,%2,%3};"
        : "+f"(c[0]), "+f"(c[1]), "+f"(c[2]), "+f"(c[3])
        : "r"(a[0]), "r"(a[1]), "r"(a[2]), "r"(a[3]), "r"(b0), "r"(b1));
}
__device__ __forceinline__ uint32_t sw128(uint32_t off) {
    return off ^ ((off >> 3) & 0x70u);
}

// ======================= Kernel 1: h = x @ W, bf16-split + transpose =======================
// smem 24.6KB -> high occupancy. x staged in two 128-col halves.
__global__ void __launch_bounds__(256)
k_gemm_h(const float* __restrict__ x, const float* __restrict__ W) {
    __shared__ float x_s[32][129];
    __shared__ float w_s[32][OUT_F];
    const int tid = threadIdx.x;
    const int ti  = tid & 31;
    const int tf  = tid >> 5;
    const int rBase = blockIdx.x * 32;

    float acc[8] = {0.f,0.f,0.f,0.f,0.f,0.f,0.f,0.f};

    #pragma unroll
    for (int xh = 0; xh < 2; xh++) {
        __syncthreads();
        // stage x cols [xh*128, xh*128+128): 1024 float4, 4 per thread
        #pragma unroll
        for (int k = 0; k < 4; k++) {
            int idx = tid + k * 256;
            int row = idx >> 5;
            int c4  = (idx & 31) << 2;
            float4 v = *reinterpret_cast<const float4*>(
                x + (size_t)(rBase + row) * IN_F + xh * 128 + c4);
            x_s[row][c4 + 0] = v.x; x_s[row][c4 + 1] = v.y;
            x_s[row][c4 + 2] = v.z; x_s[row][c4 + 3] = v.w;
        }
        for (int kc = 0; kc < 4; kc++) {
            __syncthreads();
            #pragma unroll
            for (int m = 0; m < 2; m++) {
                int idx = tid + m * 256;
                int row = idx >> 4;
                int c4  = (idx & 15) << 2;
                *reinterpret_cast<float4*>(&w_s[row][c4]) =
                    *reinterpret_cast<const float4*>(
                        W + (size_t)(xh * 128 + kc * 32 + row) * OUT_F + c4);
            }
            __syncthreads();
            #pragma unroll 8
            for (int kk = 0; kk < 32; kk++) {
                float xv = x_s[ti][kc * 32 + kk];
                float4 w0 = *reinterpret_cast<const float4*>(&w_s[kk][tf * 8]);
                float4 w1 = *reinterpret_cast<const float4*>(&w_s[kk][tf * 8 + 4]);
                acc[0] += xv * w0.x; acc[1] += xv * w0.y;
                acc[2] += xv * w0.z; acc[3] += xv * w0.w;
                acc[4] += xv * w1.x; acc[5] += xv * w1.y;
                acc[6] += xv * w1.z; acc[7] += xv * w1.w;
            }
        }
    }

    int j = rBase + ti;
    #pragma unroll
    for (int u = 0; u < 8; u++) {
        int f = tf * 8 + u;
        __nv_bfloat16 bh = __float2bfloat16(acc[u]);
        float lo = acc[u] - __bfloat162float(bh);
        __nv_bfloat16 bl = __float2bfloat16(lo);
        g_bt[(size_t)f * N_NODES + j]        = bh;
        g_bt[(size_t)(64 + f) * N_NODES + j] = bl;
    }
}

// ======================= Kernel 2: HMMA masked aggregation =======================
// partial[js][i, 0:64] = sum_{j in split} mask[i,j] * h[j,:], hi+lo combined in-register.
// CTA tile 128(i) x 128(n) x 64(k). Warps: 2M x 4N; warp owns M=64 and
// feature chunks [wn*16, wn*16+16) (hi) + [64+wn*16, ...) (lo).
// smem: A bf16 [2][128][64] @0 (32KB), B bf16 [3][128][64] @32768 (48KB)
__global__ void __launch_bounds__(256, 2)
k_aggregate(const int* __restrict__ adj) {
    extern __shared__ __align__(1024) unsigned char smem[];
    const int tid   = threadIdx.x;
    const int lane  = tid & 31;
    const int w     = tid >> 5;
    const int wm    = w & 1;          // M half (64 rows)
    const int wn    = w >> 1;         // feature chunk quarter (16 feats hi + 16 lo)
    const int iBase = blockIdx.x * BI;
    const int js    = blockIdx.y;
    const int jBeg  = js * JRANGE;

    uint32_t sbase = (smem_u32(smem) + 1023u) & ~1023u;
    const uint32_t offA = sbase;
    const uint32_t offB = sbase + 32768;

    // ---- staging geometry (single-reg swizzle bases; rows stride by k) ----
    // A: 2048 int4/tile, 8/thread: row(k)=k*16+(tid>>4), col16B=(tid&15)
    const uint32_t A_SW0 = sw128((uint32_t)((tid >> 4) * 128 + (tid & 15) * 8));
    const int4* aT = reinterpret_cast<const int4*>(
        adj + (size_t)(iBase + (tid >> 4)) * N_NODES + jBeg) + (tid & 15);
    // B: 1024 16B/tile, 4/thread: row(k)=k*32+(tid>>3), col16B=(tid&7)
    const uint32_t B_SW0 = sw128((uint32_t)((tid >> 3) * 128 + (tid & 7) * 16));
    const __nv_bfloat16* bT =
        g_bt + (size_t)(tid >> 3) * N_NODES + jBeg + (tid & 7) * 8;

    // ---- ldmatrix lane geometry ----
    const uint32_t a_ch = (uint32_t)((lane >> 4) << 4);
    const uint32_t AR0  = (uint32_t)((wm * 64 + (lane & 15)) * 128 + ((lane & 7) << 4));
    const int b_n       = (lane & 7) + ((lane >> 4) << 3);
    const uint32_t b_cb = (lane & 8) ? 16u : 0u;
    const uint32_t BR0  = (uint32_t)((wn * 16 + b_n) * 128 + ((b_n & 7) << 4));

    // ---- prologue ----
    #pragma unroll
    for (int k = 0; k < 4; k++)
        cp_async16(offB + B_SW0 + k * 4096, bT + (size_t)k * 32 * N_NODES);
    asm volatile("cp.async.commit_group;" ::: "memory");
    int4 rA[8];
    #pragma unroll
    for (int k = 0; k < 8; k++) rA[k] = __ldg(aT + (size_t)k * 16 * (N_NODES / 4));
    aT += 16;
    const __nv_bfloat16* bCur = bT + 64;

    float acc[2][4][2][4];   // [hi/lo][m-frag][n-frag][quad]
    #pragma unroll
    for (int h = 0; h < 2; h++)
        #pragma unroll
        for (int mi = 0; mi < 4; mi++)
            #pragma unroll
            for (int nj = 0; nj < 2; nj++)
                #pragma unroll
                for (int q = 0; q < 4; q++) acc[h][mi][nj][q] = 0.f;
    int dacc[8] = {0,0,0,0,0,0,0,0};

    for (int t = 0; t < NTILES; t++) {
        const uint32_t aBase = offA + (uint32_t)(t & 1) * 16384;
        const uint32_t bBase = offB + (uint32_t)(t % 3) * 16384;

        // 1. convert + STS A(t); degree via dp4a
        #pragma unroll
        for (int k = 0; k < 8; k++) {
            uint32_t t0 = __byte_perm((uint32_t)rA[k].x, (uint32_t)rA[k].y, 0x7430);
            uint32_t t1 = __byte_perm((uint32_t)rA[k].z, (uint32_t)rA[k].w, 0x7430);
            dacc[k] = __dp4a((int)t0, 0x01010101, dacc[k]);
            dacc[k] = __dp4a((int)t1, 0x01010101, dacc[k]);
            sts64(aBase + A_SW0 + (uint32_t)k * 2048, t0 * 0x3F80u, t1 * 0x3F80u);
        }
        // 2. prefetch tile t+1
        if (t + 1 < NTILES) {
            uint32_t bDst = offB + (uint32_t)((t + 1) % 3) * 16384;
            #pragma unroll
            for (int k = 0; k < 4; k++)
                cp_async16(bDst + B_SW0 + k * 4096, bCur + (size_t)k * 32 * N_NODES);
            asm volatile("cp.async.commit_group;" ::: "memory");
            bCur += 64;
            #pragma unroll
            for (int k = 0; k < 8; k++) rA[k] = __ldg(aT + (size_t)k * 16 * (N_NODES / 4));
            aT += 16;
            asm volatile("cp.async.wait_group 1;" ::: "memory");
        } else {
            asm volatile("cp.async.wait_group 0;" ::: "memory");
        }
        __syncthreads();

        // 3. MMA on tile t
        #pragma unroll
        for (int kk = 0; kk < 4; kk++) {
            const uint32_t cb = (uint32_t)(kk * 32);
            uint32_t B0[4], B1[4];
            ldsm4(B0, (bBase + BR0)        ^ (cb + b_cb));   // hi chunk
            ldsm4(B1, (bBase + BR0 + 8192) ^ (cb + b_cb));   // lo chunk
            #pragma unroll
            for (int mi = 0; mi < 4; mi++) {
                uint32_t A0[4];
                ldsm4(A0, (aBase + AR0 + (uint32_t)mi * 2048) ^ (cb + a_ch));
                mma16816(acc[0][mi][0], A0, B0[0], B0[1]);
                mma16816(acc[0][mi][1], A0, B0[2], B0[3]);
                mma16816(acc[1][mi][0], A0, B1[0], B1[1]);
                mma16816(acc[1][mi][1], A0, B1[2], B1[3]);
            }
        }
    }

    // ---- epilogue: combine hi+lo in-register, write partials directly ----
    {
        const int g8 = lane >> 2;
        const int cp = (lane & 3) * 2;
        #pragma unroll
        for (int mi = 0; mi < 4; mi++) {
            int r = iBase + wm * 64 + mi * 16 + g8;
            #pragma unroll
            for (int nj = 0; nj < 2; nj++) {
                int col = wn * 16 + nj * 8 + cp;
                float2 v0, v1;
                v0.x = acc[0][mi][nj][0] + acc[1][mi][nj][0];
                v0.y = acc[0][mi][nj][1] + acc[1][mi][nj][1];
                v1.x = acc[0][mi][nj][2] + acc[1][mi][nj][2];
                v1.y = acc[0][mi][nj][3] + acc[1][mi][nj][3];
                *reinterpret_cast<float2*>(&g_part[js][(size_t)r * OUT_F + col]) = v0;
                *reinterpret_cast<float2*>(&g_part[js][(size_t)(r + 8) * OUT_F + col]) = v1;
            }
        }
    }

    // degree: dacc[k] covers row k*16 + (tid>>4), partials across lanes (tid&15)
    #pragma unroll
    for (int k = 0; k < 8; k++) {
        int v = dacc[k];
        v += __shfl_down_sync(0xffffffffu, v, 8, 16);
        v += __shfl_down_sync(0xffffffffu, v, 4, 16);
        v += __shfl_down_sync(0xffffffffu, v, 2, 16);
        v += __shfl_down_sync(0xffffffffu, v, 1, 16);
        if ((tid & 15) == 0)
            g_deg[js][iBase + k * 16 + (tid >> 4)] = v;
    }
}

// ================ Kernel 3: out = elu(sum(partials)/deg) ================
__global__ void __launch_bounds__(256)
k_finalize(float* __restrict__ out) {
    int g = blockIdx.x * 256 + threadIdx.x;
    int i = g >> 6;
    float s = g_part[0][g] + g_part[1][g] + g_part[2][g];
    float d = (float)(g_deg[0][i] + g_deg[1][i] + g_deg[2][i]);
    float v = s / d;
    out[g] = (v > 0.f) ? v : expm1f(v);
}

// =========================== launch ===========================
#define SMEM_AGG (32768 + 49152 + 1024)

extern "C" void kernel_launch(void* const* d_in, const int* in_sizes, int n_in,
                              void* d_out, int out_size) {
    const int* adj = nullptr;
    const float* x = nullptr;
    const float* W = nullptr;
    for (int k = 0; k < n_in; k++) {
        long long sz = in_sizes[k];
        if (sz == (long long)N_NODES * N_NODES)      adj = (const int*)d_in[k];
        else if (sz == (long long)N_NODES * IN_F)    x = (const float*)d_in[k];
        else if (sz == (long long)IN_F * OUT_F)      W = (const float*)d_in[k];
    }
    float* out = (float*)d_out;

    cudaFuncSetAttribute(k_aggregate, cudaFuncAttributeMaxDynamicSharedMemorySize, SMEM_AGG);

    k_gemm_h<<<N_NODES / 32, 256>>>(x, W);
    k_aggregate<<<dim3(N_NODES / BI, JSPLIT), 256, SMEM_AGG>>>(adj);
    k_finalize<<<(N_NODES * OUT_F) / 256, 256>>>(out);
}